// round 15
// baseline (speedup 1.0000x reference)
#include <cuda_runtime.h>
#include <cuda_fp16.h>
#include <stdint.h>

// Problem constants
#define B_  4
#define T_  1024
#define K_  64
#define D_  1024
#define V_  32000
#define BT_ (B_ * T_)      // 4096 rows
#define XK_ (2 * D_)       // 2048 GEMM K dim

#define BM 128
#define BN 128

// ---------------- scratch (static device globals; no allocations) ----------
__device__ __half g_X[BT_ * XK_];       // 16 MB  (X = [q | wsk] as fp16)
__device__ __half g_Whi[XK_ * D_];      // 4 MB   (W1 hi fp16)
__device__ __half g_Wlo[XK_ * D_];      // 4 MB   (W1 lo fp16, subnormal-ok)
__device__ float  g_lam[BT_];           // lambda pre-activation accumulators
__device__ unsigned g_cnt[BT_ / BM];    // per-m-slab completion counters

// ---------------- small helpers -------------------------------------------
__device__ __forceinline__ void split_fp16(float x, __half& hi, __half& lo) {
    hi = __float2half(x);
    lo = __float2half(x - __half2float(hi));
}

__device__ __forceinline__ void cp16(void* smem_ptr, const void* gmem_ptr) {
    uint32_t sa = (uint32_t)__cvta_generic_to_shared(smem_ptr);
    asm volatile("cp.async.cg.shared.global [%0], [%1], 16;\n" :: "r"(sa), "l"(gmem_ptr));
}
#define CP_COMMIT() asm volatile("cp.async.commit_group;\n" ::: "memory")
#define CP_WAIT1()  asm volatile("cp.async.wait_group 1;\n" ::: "memory")

__device__ __forceinline__ void ldsm4(uint32_t* r, const void* p) {
    uint32_t a = (uint32_t)__cvta_generic_to_shared(p);
    asm volatile("ldmatrix.sync.aligned.m8n8.x4.shared.b16 {%0,%1,%2,%3}, [%4];\n"
                 : "=r"(r[0]), "=r"(r[1]), "=r"(r[2]), "=r"(r[3]) : "r"(a));
}

// Transposed variant for the B fragment of mma.row.col (B row-major [k][n]).
__device__ __forceinline__ void ldsm4t(uint32_t* r, const void* p) {
    uint32_t a = (uint32_t)__cvta_generic_to_shared(p);
    asm volatile("ldmatrix.sync.aligned.m8n8.x4.trans.shared.b16 {%0,%1,%2,%3}, [%4];\n"
                 : "=r"(r[0]), "=r"(r[1]), "=r"(r[2]), "=r"(r[3]) : "r"(a));
}

__device__ __forceinline__ void mma_f16(float* c, const uint32_t* a, const uint32_t* b) {
    asm volatile(
        "mma.sync.aligned.m16n8k16.row.col.f32.f16.f16.f32 "
        "{%0,%1,%2,%3},{%4,%5,%6,%7},{%8,%9},{%0,%1,%2,%3};\n"
        : "+f"(c[0]), "+f"(c[1]), "+f"(c[2]), "+f"(c[3])
        : "r"(a[0]), "r"(a[1]), "r"(a[2]), "r"(a[3]), "r"(b[0]), "r"(b[1]));
}

// ---------------- kernel 1: convert W1 to fp16 hi/lo + zero g_lam/g_cnt -----
__global__ void convw_kernel(const float* __restrict__ W1) {
    int gid = blockIdx.x * blockDim.x + threadIdx.x;
    if (gid < BT_) g_lam[gid] = 0.f;
    if (gid < BT_ / BM) g_cnt[gid] = 0u;
    const float4* W14 = (const float4*)W1;
    const int n4 = XK_ * D_ / 4;
    int stride = gridDim.x * blockDim.x;
    for (int i = gid; i < n4; i += stride) {
        float4 w = W14[i];
        __half hh[4], ll[4];
        split_fp16(w.x, hh[0], ll[0]); split_fp16(w.y, hh[1], ll[1]);
        split_fp16(w.z, hh[2], ll[2]); split_fp16(w.w, hh[3], ll[3]);
        *(uint2*)&g_Whi[i * 4] = *(uint2*)hh;
        *(uint2*)&g_Wlo[i * 4] = *(uint2*)ll;
    }
}

// ---------------- kernel 2: fused per-(b,t) pipeline ------------------------
// Two-pass structure + hybrid smem key cache, now at 4 CTAs/SM:
// pass 1 parks the first KC_ k-slices as fp16 in smem; pass 2 reads those
// from smem (no L2) and the remaining 64-KC_ slices from L2.
#define KC_ 27                                     // cached k-slices
#define FUSE_KEY_SMEM (KC_ * D_ * 2)               // 55296 B
#define FUSE_SMEM_BYTES (FUSE_KEY_SMEM + 512)      // 55808 B; 4/SM = 223.2KB
__global__ __launch_bounds__(256) void fuse_kernel(
    const float* __restrict__ q, const float* __restrict__ keys,
    const float* __restrict__ dist, const int* __restrict__ vals,
    const float* __restrict__ Wb, const float* __restrict__ bbp,
    float* __restrict__ probs)
{
    extern __shared__ __align__(16) char fsmem[];
    __half* skeys   = (__half*)fsmem;                      // [KC_][1024] fp16
    float*  s_red   = (float*)(fsmem + FUSE_KEY_SMEM);     // 8
    float*  s_w     = s_red + 8;                           // 64
    float*  s_invbw = s_w + K_;                            // 1

    const int tid = threadIdx.x;
    const float4* Wb4 = (const float4*)Wb;
    const float4 wbq = Wb4[tid];           // Wb[0:1024) chunk
    const float4 wbk = Wb4[256 + tid];     // Wb[1024:2048) chunk

    for (int row = blockIdx.x; row < BT_; row += gridDim.x) {
        const float4* qr4 = (const float4*)(q + (size_t)row * D_);
        const float4* kr4 = (const float4*)(keys + (size_t)row * K_ * D_);

        // ---- zero this row's vocab slice (evict-first: don't pollute L2)
        {
            float4 z = make_float4(0.f, 0.f, 0.f, 0.f);
            float4* pr = (float4*)(probs + (size_t)row * V_);
            #pragma unroll 4
            for (int i = tid; i < V_ / 4; i += 256) __stcs(pr + i, z);
        }

        // ---- pass 1: column sums over K (streams keys from DRAM).
        //      k < KC_ : evict-first read (dead in L2), fp16 copy -> smem
        //      k >= KC_: default read (stays in L2 for pass 2)
        float4 ks = make_float4(0.f, 0.f, 0.f, 0.f);
        #pragma unroll 4
        for (int k = 0; k < KC_; k++) {
            float4 v = __ldcs(&kr4[k * (D_ / 4) + tid]);
            ks.x += v.x; ks.y += v.y; ks.z += v.z; ks.w += v.w;
            __half2 h0 = __floats2half2_rn(v.x, v.y);
            __half2 h1 = __floats2half2_rn(v.z, v.w);
            uint2 pk;
            pk.x = *(uint32_t*)&h0;
            pk.y = *(uint32_t*)&h1;
            *(uint2*)&skeys[k * D_ + 4 * tid] = pk;   // own-write, own-read later
        }
        #pragma unroll 4
        for (int k = KC_; k < K_; k++) {
            float4 v = kr4[k * (D_ / 4) + tid];
            ks.x += v.x; ks.y += v.y; ks.z += v.z; ks.w += v.w;
        }
        const float4 q4 = qr4[tid];
        float part = q4.x * wbq.x + q4.y * wbq.y + q4.z * wbq.z + q4.w * wbq.w;
        part += (1.0f / K_) * (ks.x * wbk.x + ks.y * wbk.y + ks.z * wbk.z + ks.w * wbk.w);

        // block reduce -> bandwidth input
        #pragma unroll
        for (int o = 16; o > 0; o >>= 1) part += __shfl_xor_sync(0xffffffffu, part, o);
        if ((tid & 31) == 0) s_red[tid >> 5] = part;
        __syncthreads();                          // B1 (also orders row zeroing)
        if (tid < 32) {
            float v = (tid < 8) ? s_red[tid] : 0.f;
            #pragma unroll
            for (int o = 4; o > 0; o >>= 1) v += __shfl_xor_sync(0xffffffffu, v, o);
            if (tid == 0) s_invbw[0] = __expf(-(v + bbp[0]));   // 1 / bandwidth
        }
        __syncthreads();                          // B2
        const float invbw = s_invbw[0];

        // ---- softmax over K (warp 0, 2 entries per lane)
        if (tid < 32) {
            float a0 = -sqrtf(dist[(size_t)row * K_ + tid])      * invbw;
            float a1 = -sqrtf(dist[(size_t)row * K_ + tid + 32]) * invbw;
            float m = fmaxf(a0, a1);
            #pragma unroll
            for (int o = 16; o > 0; o >>= 1) m = fmaxf(m, __shfl_xor_sync(0xffffffffu, m, o));
            float e0 = __expf(a0 - m), e1 = __expf(a1 - m);
            float s = e0 + e1;
            #pragma unroll
            for (int o = 16; o > 0; o >>= 1) s += __shfl_xor_sync(0xffffffffu, s, o);
            float inv = 1.0f / s;
            s_w[tid] = e0 * inv;
            s_w[tid + 32] = e1 * inv;
        }
        __syncthreads();                          // B3 (zero visible before scatter)

        // ---- scatter weights into vocab row
        if (tid < K_) {
            int v = vals[(size_t)row * K_ + tid];
            atomicAdd(&probs[(size_t)row * V_ + v], s_w[tid]);
        }

        // ---- pass 2: weighted key sum. Cached slices from smem (no L2),
        //      remainder from L2 (evict-first, data dead after).
        float4 ws = make_float4(0.f, 0.f, 0.f, 0.f);
        #pragma unroll 4
        for (int k = 0; k < KC_; k++) {
            uint2 pk = *(uint2*)&skeys[k * D_ + 4 * tid];
            float2 v01 = __half22float2(*(__half2*)&pk.x);
            float2 v23 = __half22float2(*(__half2*)&pk.y);
            const float wk = s_w[k];
            ws.x = fmaf(wk, v01.x, ws.x);
            ws.y = fmaf(wk, v01.y, ws.y);
            ws.z = fmaf(wk, v23.x, ws.z);
            ws.w = fmaf(wk, v23.y, ws.w);
        }
        #pragma unroll 4
        for (int k = KC_; k < K_; k++) {
            float4 v = __ldcs(&kr4[k * (D_ / 4) + tid]);
            const float wk = s_w[k];
            ws.x = fmaf(wk, v.x, ws.x);
            ws.y = fmaf(wk, v.y, ws.y);
            ws.z = fmaf(wk, v.z, ws.z);
            ws.w = fmaf(wk, v.w, ws.w);
        }

        // ---- write X = [q | wsk] as fp16 (8B packed stores)
        const size_t xb = (size_t)row * XK_ + 4 * tid;
        __half hh[4];
        hh[0] = __float2half(q4.x); hh[1] = __float2half(q4.y);
        hh[2] = __float2half(q4.z); hh[3] = __float2half(q4.w);
        *(uint2*)&g_X[xb] = *(uint2*)hh;
        hh[0] = __float2half(ws.x); hh[1] = __float2half(ws.y);
        hh[2] = __float2half(ws.z); hh[3] = __float2half(ws.w);
        *(uint2*)&g_X[xb + D_] = *(uint2*)hh;
        // no end-of-row barrier needed: next-row s_w rewrite is gated by B1/B2,
        // and skeys slots are thread-private.
    }
}

// ---------------- kernel 3: GEMM relu(X @ W1 + b1) -> lambda -> sigmoid -----
// Proven BKg=32 fp16 2-term shape, now 3-stage cp.async pipelined:
//   acc = X*Whi + X*Wlo      (fp32 accumulate; X carries u=2^-11 rounding)
// Epilogue accumulates h.W2 into g_lam; the LAST CTA of each m-slab (via
// completion counter) applies the sigmoid and writes the output directly.
#define BKg 32
#define ASTR 40        // 32 + 8 pad (80B row stride: conflict-free ldmatrix)
#define BSTR 136       // 128 + 8 pad (272B row stride)
#define A_TILE (BM * ASTR)    // 5120 elems
#define B_TILE (BKg * BSTR)   // 4352 elems
#define STAGES 3
#define GEMM_SMEM_BYTES ((STAGES * A_TILE + 2 * STAGES * B_TILE) * 2)  // 82944 B

__device__ __forceinline__ void gemm_load_stage(
    __half* sA, __half* sBhi, __half* sBlo, int m0, int n0, int kt, int tid)
{
    // A tile: 128x32 fp16, two uint4 rows per thread
    int rA = tid >> 2, cA = (tid & 3) * 8;
    size_t gA = (size_t)(m0 + rA) * XK_ + (size_t)kt * BKg + cA;
    cp16(sA + rA * ASTR + cA, g_X + gA);
    cp16(sA + (rA + 64) * ASTR + cA, g_X + gA + (size_t)64 * XK_);
    // B tiles: 32x128 fp16
    int rB = tid >> 4, cB = (tid & 15) * 8;
    size_t gB = (size_t)(kt * BKg + rB) * D_ + n0 + cB;
    cp16(sBhi + rB * BSTR + cB, g_Whi + gB);
    cp16(sBlo + rB * BSTR + cB, g_Wlo + gB);
    size_t gB2 = gB + (size_t)16 * D_;
    cp16(sBhi + (rB + 16) * BSTR + cB, g_Whi + gB2);
    cp16(sBlo + (rB + 16) * BSTR + cB, g_Wlo + gB2);
}

__global__ __launch_bounds__(256, 2) void gemm_kernel(
    const float* __restrict__ b1, const float* __restrict__ W2,
    const float* __restrict__ b2, float* __restrict__ out)
{
    extern __shared__ __half smem[];
    __half* sA    = smem;                               // [STAGES][A_TILE]
    __half* sB_hi = smem + STAGES * A_TILE;             // [STAGES][B_TILE]
    __half* sB_lo = smem + STAGES * A_TILE + STAGES * B_TILE;

    const int tid  = threadIdx.x;
    const int warp = tid >> 5;
    const int lane = tid & 31;
    const int m0 = blockIdx.y * BM;
    const int n0 = blockIdx.x * BN;
    const int wm = warp >> 2;      // 0..1 -> 64-row slab
    const int wn = warp & 3;       // 0..3 -> 32-col slab

    float acc[4][4][4];
    #pragma unroll
    for (int i = 0; i < 4; i++)
        #pragma unroll
        for (int j = 0; j < 4; j++)
            #pragma unroll
            for (int r = 0; r < 4; r++) acc[i][j][r] = 0.f;

    const int NT = XK_ / BKg;  // 64
    // prologue: stages 0 and 1 in flight as separate groups
    gemm_load_stage(sA, sB_hi, sB_lo, m0, n0, 0, tid);
    CP_COMMIT();
    gemm_load_stage(sA + A_TILE, sB_hi + B_TILE, sB_lo + B_TILE, m0, n0, 1, tid);
    CP_COMMIT();

    int st = 0, pf = 2;   // compute stage, prefetch stage
    for (int kt = 0; kt < NT; kt++) {
        CP_WAIT1();            // group kt complete (<=1 group pending)
        __syncthreads();       // all warps done with stage pf's previous contents

        if (kt + 2 < NT)
            gemm_load_stage(sA + pf * A_TILE, sB_hi + pf * B_TILE,
                            sB_lo + pf * B_TILE, m0, n0, kt + 2, tid);
        CP_COMMIT();           // commit (possibly empty) to keep group counts aligned

        const __half* A  = sA    + st * A_TILE;
        const __half* Bh = sB_hi + st * B_TILE;
        const __half* Bl = sB_lo + st * B_TILE;

        #pragma unroll
        for (int ks = 0; ks < 2; ks++) {           // 2 k-steps of 16
            uint32_t ar[4][4];
            #pragma unroll
            for (int mi = 0; mi < 4; mi++) {
                int off = (wm * 64 + mi * 16 + (lane & 15)) * ASTR + ks * 16 + (lane >> 4) * 8;
                ldsm4(ar[mi], A + off);
            }
            uint32_t bh[4][2], bl[4][2];
            #pragma unroll
            for (int nj = 0; nj < 2; nj++) {
                int off = (ks * 16 + (lane & 15)) * BSTR + wn * 32 + nj * 16 + (lane >> 4) * 8;
                uint32_t r[4];
                ldsm4t(r, Bh + off);
                bh[2 * nj][0] = r[0]; bh[2 * nj][1] = r[1];
                bh[2 * nj + 1][0] = r[2]; bh[2 * nj + 1][1] = r[3];
                ldsm4t(r, Bl + off);
                bl[2 * nj][0] = r[0]; bl[2 * nj][1] = r[1];
                bl[2 * nj + 1][0] = r[2]; bl[2 * nj + 1][1] = r[3];
            }
            #pragma unroll
            for (int mi = 0; mi < 4; mi++)
                #pragma unroll
                for (int ni = 0; ni < 4; ni++) {
                    mma_f16(acc[mi][ni], ar[mi], bh[ni]);   // X * Whi
                    mma_f16(acc[mi][ni], ar[mi], bl[ni]);   // X * Wlo
                }
        }
        st = (st == STAGES - 1) ? 0 : st + 1;
        pf = (pf == STAGES - 1) ? 0 : pf + 1;
    }
    __syncthreads();   // tiles dead before smem reuse below

    // epilogue: h = relu(acc + b1); lambda partial = h . W2 over this CTA's cols
    const int g = lane >> 2;
    const int t2 = (lane & 3) * 2;
    float part0[4] = {0.f, 0.f, 0.f, 0.f};   // rows wm*64 + mi*16 + g
    float part1[4] = {0.f, 0.f, 0.f, 0.f};   // rows wm*64 + mi*16 + g + 8
    #pragma unroll
    for (int ni = 0; ni < 4; ni++) {
        const int cw = n0 + wn * 32 + ni * 8 + t2;
        const float bia0 = b1[cw], bia1 = b1[cw + 1];
        const float w20 = W2[cw], w21 = W2[cw + 1];
        #pragma unroll
        for (int mi = 0; mi < 4; mi++) {
            float v00 = fmaxf(acc[mi][ni][0] + bia0, 0.f);
            float v01 = fmaxf(acc[mi][ni][1] + bia1, 0.f);
            float v10 = fmaxf(acc[mi][ni][2] + bia0, 0.f);
            float v11 = fmaxf(acc[mi][ni][3] + bia1, 0.f);
            part0[mi] += v00 * w20 + v01 * w21;
            part1[mi] += v10 * w20 + v11 * w21;
        }
    }
    // reduce over the 4 lanes of each quad-group (lane bits 0..1)
    #pragma unroll
    for (int mi = 0; mi < 4; mi++) {
        part0[mi] += __shfl_xor_sync(0xffffffffu, part0[mi], 1);
        part0[mi] += __shfl_xor_sync(0xffffffffu, part0[mi], 2);
        part1[mi] += __shfl_xor_sync(0xffffffffu, part1[mi], 1);
        part1[mi] += __shfl_xor_sync(0xffffffffu, part1[mi], 2);
    }
    // accumulate across the 4 wn-warps via smem, then one global atomic per row
    float* s_lam = (float*)smem;   // tiles are dead (sync above)
    if (tid < BM) s_lam[tid] = 0.f;
    __syncthreads();
    if ((lane & 3) == 0) {
        #pragma unroll
        for (int mi = 0; mi < 4; mi++) {
            atomicAdd(&s_lam[wm * 64 + mi * 16 + g], part0[mi]);
            atomicAdd(&s_lam[wm * 64 + mi * 16 + g + 8], part1[mi]);
        }
    }
    __syncthreads();
    if (tid < BM) atomicAdd(&g_lam[m0 + tid], s_lam[tid]);

    // ---- completion counter: last CTA of this m-slab applies the sigmoid
    __shared__ unsigned s_last;
    __threadfence();               // release: my g_lam adds visible device-wide
    __syncthreads();               // all threads' adds happen-before tid0's inc
    if (tid == 0)
        s_last = (atomicInc(&g_cnt[blockIdx.y], 0xFFFFFFFFu) == (unsigned)(gridDim.x - 1));
    __syncthreads();
    if (s_last && tid < BM) {
        __threadfence();           // acquire side
        float z = __ldcg(&g_lam[m0 + tid]) + b2[0];
        out[(size_t)BT_ * V_ + m0 + tid] = 1.0f / (1.0f + __expf(-z));
    }
}

// ---------------- launch ----------------------------------------------------
extern "C" void kernel_launch(void* const* d_in, const int* in_sizes, int n_in,
                              void* d_out, int out_size)
{
    const float* q    = (const float*)d_in[0];
    const float* keys = (const float*)d_in[1];
    const float* dist = (const float*)d_in[2];
    const int*   vals = (const int*)d_in[3];
    const float* Wb   = (const float*)d_in[4];
    const float* bb   = (const float*)d_in[5];
    const float* W1   = (const float*)d_in[6];
    const float* b1   = (const float*)d_in[7];
    const float* W2   = (const float*)d_in[8];
    const float* b2   = (const float*)d_in[9];
    float* out = (float*)d_out;

    cudaFuncSetAttribute(gemm_kernel, cudaFuncAttributeMaxDynamicSharedMemorySize,
                         GEMM_SMEM_BYTES);
    cudaFuncSetAttribute(fuse_kernel, cudaFuncAttributeMaxDynamicSharedMemorySize,
                         FUSE_SMEM_BYTES);

    // 1. convert W1 to fp16 hi/lo; zero lambda accumulators + counters
    convw_kernel<<<2048, 256>>>(W1);

    // 2. fused zero+bandwidth+softmax+scatter+weighted-sum (persistent,
    //    4 CTAs/SM; 27/64 k-slices cached fp16 in smem for pass 2)
    fuse_kernel<<<592, 256, FUSE_SMEM_BYTES>>>(q, keys, dist, vals, Wb, bb, out);

    // 3. relu(X @ W1 + b1) via fp16 2-term MMA, 3-stage pipeline; epilogue
    //    accumulates h.W2 and the last CTA per m-slab writes sigmoid(lambda)
    gemm_kernel<<<dim3(D_ / BN, BT_ / BM), 256, GEMM_SMEM_BYTES>>>(b1, W2, b2, out);
}

// round 17
// speedup vs baseline: 1.0362x; 1.0362x over previous
#include <cuda_runtime.h>
#include <cuda_fp16.h>
#include <stdint.h>

// Problem constants
#define B_  4
#define T_  1024
#define K_  64
#define D_  1024
#define V_  32000
#define BT_ (B_ * T_)      // 4096 rows
#define XK_ (2 * D_)       // 2048 GEMM K dim

#define BM 128
#define BN 128

// ---------------- scratch (static device globals; no allocations) ----------
__device__ __half g_X[BT_ * XK_];       // 16 MB  (X = [q | wsk] as fp16)
__device__ __half g_Whi[XK_ * D_];      // 4 MB   (W1 hi fp16)
__device__ __half g_Wlo[XK_ * D_];      // 4 MB   (W1 lo fp16, subnormal-ok)
__device__ float  g_lam[BT_];           // lambda pre-activation accumulators
__device__ unsigned g_cnt[BT_ / BM];    // per-m-slab completion counters

// ---------------- small helpers -------------------------------------------
__device__ __forceinline__ void split_fp16(float x, __half& hi, __half& lo) {
    hi = __float2half(x);
    lo = __float2half(x - __half2float(hi));
}

__device__ __forceinline__ void cp16(void* smem_ptr, const void* gmem_ptr) {
    uint32_t sa = (uint32_t)__cvta_generic_to_shared(smem_ptr);
    asm volatile("cp.async.cg.shared.global [%0], [%1], 16;\n" :: "r"(sa), "l"(gmem_ptr));
}
#define CP_COMMIT() asm volatile("cp.async.commit_group;\n" ::: "memory")
#define CP_WAIT1()  asm volatile("cp.async.wait_group 1;\n" ::: "memory")

__device__ __forceinline__ void ldsm4(uint32_t* r, const void* p) {
    uint32_t a = (uint32_t)__cvta_generic_to_shared(p);
    asm volatile("ldmatrix.sync.aligned.m8n8.x4.shared.b16 {%0,%1,%2,%3}, [%4];\n"
                 : "=r"(r[0]), "=r"(r[1]), "=r"(r[2]), "=r"(r[3]) : "r"(a));
}

// Transposed variant for the B fragment of mma.row.col (B row-major [k][n]).
__device__ __forceinline__ void ldsm4t(uint32_t* r, const void* p) {
    uint32_t a = (uint32_t)__cvta_generic_to_shared(p);
    asm volatile("ldmatrix.sync.aligned.m8n8.x4.trans.shared.b16 {%0,%1,%2,%3}, [%4];\n"
                 : "=r"(r[0]), "=r"(r[1]), "=r"(r[2]), "=r"(r[3]) : "r"(a));
}

__device__ __forceinline__ void mma_f16(float* c, const uint32_t* a, const uint32_t* b) {
    asm volatile(
        "mma.sync.aligned.m16n8k16.row.col.f32.f16.f16.f32 "
        "{%0,%1,%2,%3},{%4,%5,%6,%7},{%8,%9},{%0,%1,%2,%3};\n"
        : "+f"(c[0]), "+f"(c[1]), "+f"(c[2]), "+f"(c[3])
        : "r"(a[0]), "r"(a[1]), "r"(a[2]), "r"(a[3]), "r"(b[0]), "r"(b[1]));
}

// ---------------- kernel 1: convert W1 to fp16 hi/lo + zero g_lam/g_cnt -----
__global__ void convw_kernel(const float* __restrict__ W1) {
    int gid = blockIdx.x * blockDim.x + threadIdx.x;
    if (gid < BT_) g_lam[gid] = 0.f;
    if (gid < BT_ / BM) g_cnt[gid] = 0u;
    const float4* W14 = (const float4*)W1;
    const int n4 = XK_ * D_ / 4;
    int stride = gridDim.x * blockDim.x;
    for (int i = gid; i < n4; i += stride) {
        float4 w = W14[i];
        __half hh[4], ll[4];
        split_fp16(w.x, hh[0], ll[0]); split_fp16(w.y, hh[1], ll[1]);
        split_fp16(w.z, hh[2], ll[2]); split_fp16(w.w, hh[3], ll[3]);
        *(uint2*)&g_Whi[i * 4] = *(uint2*)hh;
        *(uint2*)&g_Wlo[i * 4] = *(uint2*)ll;
    }
}

// ---------------- kernel 2: fused per-(b,t) pipeline ------------------------
// R14-committed configuration: 3 CTAs/SM, two-pass + hybrid smem key cache.
// pass 1 parks the first KC_ k-slices as fp16 in smem; pass 2 reads those
// from smem (no L2) and only the remaining 64-KC_ slices from L2.
#define KC_ 36                                     // cached k-slices
#define FUSE_KEY_SMEM (KC_ * D_ * 2)               // 73728 B
#define FUSE_SMEM_BYTES (FUSE_KEY_SMEM + 512)      // 74240 B; 3/SM = 222.7KB
__global__ __launch_bounds__(256) void fuse_kernel(
    const float* __restrict__ q, const float* __restrict__ keys,
    const float* __restrict__ dist, const int* __restrict__ vals,
    const float* __restrict__ Wb, const float* __restrict__ bbp,
    float* __restrict__ probs)
{
    extern __shared__ __align__(16) char fsmem[];
    __half* skeys   = (__half*)fsmem;                      // [KC_][1024] fp16
    float*  s_red   = (float*)(fsmem + FUSE_KEY_SMEM);     // 8
    float*  s_w     = s_red + 8;                           // 64
    float*  s_invbw = s_w + K_;                            // 1

    const int tid = threadIdx.x;
    const float4* Wb4 = (const float4*)Wb;
    const float4 wbq = Wb4[tid];           // Wb[0:1024) chunk
    const float4 wbk = Wb4[256 + tid];     // Wb[1024:2048) chunk

    for (int row = blockIdx.x; row < BT_; row += gridDim.x) {
        const float4* qr4 = (const float4*)(q + (size_t)row * D_);
        const float4* kr4 = (const float4*)(keys + (size_t)row * K_ * D_);

        // ---- zero this row's vocab slice (evict-first: don't pollute L2)
        {
            float4 z = make_float4(0.f, 0.f, 0.f, 0.f);
            float4* pr = (float4*)(probs + (size_t)row * V_);
            #pragma unroll 4
            for (int i = tid; i < V_ / 4; i += 256) __stcs(pr + i, z);
        }

        // ---- pass 1: column sums over K (streams keys from DRAM).
        //      k < KC_ : evict-first read (dead in L2), fp16 copy -> smem
        //      k >= KC_: default read (stays in L2 for pass 2)
        float4 ks = make_float4(0.f, 0.f, 0.f, 0.f);
        #pragma unroll 4
        for (int k = 0; k < KC_; k++) {
            float4 v = __ldcs(&kr4[k * (D_ / 4) + tid]);
            ks.x += v.x; ks.y += v.y; ks.z += v.z; ks.w += v.w;
            __half2 h0 = __floats2half2_rn(v.x, v.y);
            __half2 h1 = __floats2half2_rn(v.z, v.w);
            uint2 pk;
            pk.x = *(uint32_t*)&h0;
            pk.y = *(uint32_t*)&h1;
            *(uint2*)&skeys[k * D_ + 4 * tid] = pk;   // own-write, own-read later
        }
        #pragma unroll 4
        for (int k = KC_; k < K_; k++) {
            float4 v = kr4[k * (D_ / 4) + tid];
            ks.x += v.x; ks.y += v.y; ks.z += v.z; ks.w += v.w;
        }
        const float4 q4 = qr4[tid];
        float part = q4.x * wbq.x + q4.y * wbq.y + q4.z * wbq.z + q4.w * wbq.w;
        part += (1.0f / K_) * (ks.x * wbk.x + ks.y * wbk.y + ks.z * wbk.z + ks.w * wbk.w);

        // block reduce -> bandwidth input
        #pragma unroll
        for (int o = 16; o > 0; o >>= 1) part += __shfl_xor_sync(0xffffffffu, part, o);
        if ((tid & 31) == 0) s_red[tid >> 5] = part;
        __syncthreads();                          // B1 (also orders row zeroing)
        if (tid < 32) {
            float v = (tid < 8) ? s_red[tid] : 0.f;
            #pragma unroll
            for (int o = 4; o > 0; o >>= 1) v += __shfl_xor_sync(0xffffffffu, v, o);
            if (tid == 0) s_invbw[0] = __expf(-(v + bbp[0]));   // 1 / bandwidth
        }
        __syncthreads();                          // B2
        const float invbw = s_invbw[0];

        // ---- softmax over K (warp 0, 2 entries per lane)
        if (tid < 32) {
            float a0 = -sqrtf(dist[(size_t)row * K_ + tid])      * invbw;
            float a1 = -sqrtf(dist[(size_t)row * K_ + tid + 32]) * invbw;
            float m = fmaxf(a0, a1);
            #pragma unroll
            for (int o = 16; o > 0; o >>= 1) m = fmaxf(m, __shfl_xor_sync(0xffffffffu, m, o));
            float e0 = __expf(a0 - m), e1 = __expf(a1 - m);
            float s = e0 + e1;
            #pragma unroll
            for (int o = 16; o > 0; o >>= 1) s += __shfl_xor_sync(0xffffffffu, s, o);
            float inv = 1.0f / s;
            s_w[tid] = e0 * inv;
            s_w[tid + 32] = e1 * inv;
        }
        __syncthreads();                          // B3 (zero visible before scatter)

        // ---- scatter weights into vocab row
        if (tid < K_) {
            int v = vals[(size_t)row * K_ + tid];
            atomicAdd(&probs[(size_t)row * V_ + v], s_w[tid]);
        }

        // ---- pass 2: weighted key sum. Cached slices from smem (no L2),
        //      remainder from L2 (evict-first, data dead after).
        float4 ws = make_float4(0.f, 0.f, 0.f, 0.f);
        #pragma unroll 4
        for (int k = 0; k < KC_; k++) {
            uint2 pk = *(uint2*)&skeys[k * D_ + 4 * tid];
            float2 v01 = __half22float2(*(__half2*)&pk.x);
            float2 v23 = __half22float2(*(__half2*)&pk.y);
            const float wk = s_w[k];
            ws.x = fmaf(wk, v01.x, ws.x);
            ws.y = fmaf(wk, v01.y, ws.y);
            ws.z = fmaf(wk, v23.x, ws.z);
            ws.w = fmaf(wk, v23.y, ws.w);
        }
        #pragma unroll 4
        for (int k = KC_; k < K_; k++) {
            float4 v = __ldcs(&kr4[k * (D_ / 4) + tid]);
            const float wk = s_w[k];
            ws.x = fmaf(wk, v.x, ws.x);
            ws.y = fmaf(wk, v.y, ws.y);
            ws.z = fmaf(wk, v.z, ws.z);
            ws.w = fmaf(wk, v.w, ws.w);
        }

        // ---- write X = [q | wsk] as fp16 (8B packed stores)
        const size_t xb = (size_t)row * XK_ + 4 * tid;
        __half hh[4];
        hh[0] = __float2half(q4.x); hh[1] = __float2half(q4.y);
        hh[2] = __float2half(q4.z); hh[3] = __float2half(q4.w);
        *(uint2*)&g_X[xb] = *(uint2*)hh;
        hh[0] = __float2half(ws.x); hh[1] = __float2half(ws.y);
        hh[2] = __float2half(ws.z); hh[3] = __float2half(ws.w);
        *(uint2*)&g_X[xb + D_] = *(uint2*)hh;
        // no end-of-row barrier needed: next-row s_w rewrite is gated by B1/B2,
        // and skeys slots are thread-private.
    }
}

// ---------------- kernel 3: GEMM relu(X @ W1 + b1) -> lambda -> sigmoid -----
// Proven BKg=32 fp16 2-term shape, 3-stage cp.async pipelined (under test):
//   acc = X*Whi + X*Wlo      (fp32 accumulate; X carries u=2^-11 rounding)
// Epilogue accumulates h.W2 into g_lam; the LAST CTA of each m-slab (via
// completion counter) applies the sigmoid and writes the output directly.
#define BKg 32
#define ASTR 40        // 32 + 8 pad (80B row stride: conflict-free ldmatrix)
#define BSTR 136       // 128 + 8 pad (272B row stride)
#define A_TILE (BM * ASTR)    // 5120 elems
#define B_TILE (BKg * BSTR)   // 4352 elems
#define STAGES 3
#define GEMM_SMEM_BYTES ((STAGES * A_TILE + 2 * STAGES * B_TILE) * 2)  // 82944 B

__device__ __forceinline__ void gemm_load_stage(
    __half* sA, __half* sBhi, __half* sBlo, int m0, int n0, int kt, int tid)
{
    // A tile: 128x32 fp16, two uint4 rows per thread
    int rA = tid >> 2, cA = (tid & 3) * 8;
    size_t gA = (size_t)(m0 + rA) * XK_ + (size_t)kt * BKg + cA;
    cp16(sA + rA * ASTR + cA, g_X + gA);
    cp16(sA + (rA + 64) * ASTR + cA, g_X + gA + (size_t)64 * XK_);
    // B tiles: 32x128 fp16
    int rB = tid >> 4, cB = (tid & 15) * 8;
    size_t gB = (size_t)(kt * BKg + rB) * D_ + n0 + cB;
    cp16(sBhi + rB * BSTR + cB, g_Whi + gB);
    cp16(sBlo + rB * BSTR + cB, g_Wlo + gB);
    size_t gB2 = gB + (size_t)16 * D_;
    cp16(sBhi + (rB + 16) * BSTR + cB, g_Whi + gB2);
    cp16(sBlo + (rB + 16) * BSTR + cB, g_Wlo + gB2);
}

__global__ __launch_bounds__(256, 2) void gemm_kernel(
    const float* __restrict__ b1, const float* __restrict__ W2,
    const float* __restrict__ b2, float* __restrict__ out)
{
    extern __shared__ __half smem[];
    __half* sA    = smem;                               // [STAGES][A_TILE]
    __half* sB_hi = smem + STAGES * A_TILE;             // [STAGES][B_TILE]
    __half* sB_lo = smem + STAGES * A_TILE + STAGES * B_TILE;

    const int tid  = threadIdx.x;
    const int warp = tid >> 5;
    const int lane = tid & 31;
    const int m0 = blockIdx.y * BM;
    const int n0 = blockIdx.x * BN;
    const int wm = warp >> 2;      // 0..1 -> 64-row slab
    const int wn = warp & 3;       // 0..3 -> 32-col slab

    float acc[4][4][4];
    #pragma unroll
    for (int i = 0; i < 4; i++)
        #pragma unroll
        for (int j = 0; j < 4; j++)
            #pragma unroll
            for (int r = 0; r < 4; r++) acc[i][j][r] = 0.f;

    const int NT = XK_ / BKg;  // 64
    // prologue: stages 0 and 1 in flight as separate groups
    gemm_load_stage(sA, sB_hi, sB_lo, m0, n0, 0, tid);
    CP_COMMIT();
    gemm_load_stage(sA + A_TILE, sB_hi + B_TILE, sB_lo + B_TILE, m0, n0, 1, tid);
    CP_COMMIT();

    int st = 0, pf = 2;   // compute stage, prefetch stage
    for (int kt = 0; kt < NT; kt++) {
        CP_WAIT1();            // group kt complete (<=1 group pending)
        __syncthreads();       // all warps done with stage pf's previous contents

        if (kt + 2 < NT)
            gemm_load_stage(sA + pf * A_TILE, sB_hi + pf * B_TILE,
                            sB_lo + pf * B_TILE, m0, n0, kt + 2, tid);
        CP_COMMIT();           // commit (possibly empty) to keep group counts aligned

        const __half* A  = sA    + st * A_TILE;
        const __half* Bh = sB_hi + st * B_TILE;
        const __half* Bl = sB_lo + st * B_TILE;

        #pragma unroll
        for (int ks = 0; ks < 2; ks++) {           // 2 k-steps of 16
            uint32_t ar[4][4];
            #pragma unroll
            for (int mi = 0; mi < 4; mi++) {
                int off = (wm * 64 + mi * 16 + (lane & 15)) * ASTR + ks * 16 + (lane >> 4) * 8;
                ldsm4(ar[mi], A + off);
            }
            uint32_t bh[4][2], bl[4][2];
            #pragma unroll
            for (int nj = 0; nj < 2; nj++) {
                int off = (ks * 16 + (lane & 15)) * BSTR + wn * 32 + nj * 16 + (lane >> 4) * 8;
                uint32_t r[4];
                ldsm4t(r, Bh + off);
                bh[2 * nj][0] = r[0]; bh[2 * nj][1] = r[1];
                bh[2 * nj + 1][0] = r[2]; bh[2 * nj + 1][1] = r[3];
                ldsm4t(r, Bl + off);
                bl[2 * nj][0] = r[0]; bl[2 * nj][1] = r[1];
                bl[2 * nj + 1][0] = r[2]; bl[2 * nj + 1][1] = r[3];
            }
            #pragma unroll
            for (int mi = 0; mi < 4; mi++)
                #pragma unroll
                for (int ni = 0; ni < 4; ni++) {
                    mma_f16(acc[mi][ni], ar[mi], bh[ni]);   // X * Whi
                    mma_f16(acc[mi][ni], ar[mi], bl[ni]);   // X * Wlo
                }
        }
        st = (st == STAGES - 1) ? 0 : st + 1;
        pf = (pf == STAGES - 1) ? 0 : pf + 1;
    }
    __syncthreads();   // tiles dead before smem reuse below

    // epilogue: h = relu(acc + b1); lambda partial = h . W2 over this CTA's cols
    const int g = lane >> 2;
    const int t2 = (lane & 3) * 2;
    float part0[4] = {0.f, 0.f, 0.f, 0.f};   // rows wm*64 + mi*16 + g
    float part1[4] = {0.f, 0.f, 0.f, 0.f};   // rows wm*64 + mi*16 + g + 8
    #pragma unroll
    for (int ni = 0; ni < 4; ni++) {
        const int cw = n0 + wn * 32 + ni * 8 + t2;
        const float bia0 = b1[cw], bia1 = b1[cw + 1];
        const float w20 = W2[cw], w21 = W2[cw + 1];
        #pragma unroll
        for (int mi = 0; mi < 4; mi++) {
            float v00 = fmaxf(acc[mi][ni][0] + bia0, 0.f);
            float v01 = fmaxf(acc[mi][ni][1] + bia1, 0.f);
            float v10 = fmaxf(acc[mi][ni][2] + bia0, 0.f);
            float v11 = fmaxf(acc[mi][ni][3] + bia1, 0.f);
            part0[mi] += v00 * w20 + v01 * w21;
            part1[mi] += v10 * w20 + v11 * w21;
        }
    }
    // reduce over the 4 lanes of each quad-group (lane bits 0..1)
    #pragma unroll
    for (int mi = 0; mi < 4; mi++) {
        part0[mi] += __shfl_xor_sync(0xffffffffu, part0[mi], 1);
        part0[mi] += __shfl_xor_sync(0xffffffffu, part0[mi], 2);
        part1[mi] += __shfl_xor_sync(0xffffffffu, part1[mi], 1);
        part1[mi] += __shfl_xor_sync(0xffffffffu, part1[mi], 2);
    }
    // accumulate across the 4 wn-warps via smem, then one global atomic per row
    float* s_lam = (float*)smem;   // tiles are dead (sync above)
    if (tid < BM) s_lam[tid] = 0.f;
    __syncthreads();
    if ((lane & 3) == 0) {
        #pragma unroll
        for (int mi = 0; mi < 4; mi++) {
            atomicAdd(&s_lam[wm * 64 + mi * 16 + g], part0[mi]);
            atomicAdd(&s_lam[wm * 64 + mi * 16 + g + 8], part1[mi]);
        }
    }
    __syncthreads();
    if (tid < BM) atomicAdd(&g_lam[m0 + tid], s_lam[tid]);

    // ---- completion counter: last CTA of this m-slab applies the sigmoid
    __shared__ unsigned s_last;
    __threadfence();               // release: my g_lam adds visible device-wide
    __syncthreads();               // all threads' adds happen-before tid0's inc
    if (tid == 0)
        s_last = (atomicInc(&g_cnt[blockIdx.y], 0xFFFFFFFFu) == (unsigned)(gridDim.x - 1));
    __syncthreads();
    if (s_last && tid < BM) {
        __threadfence();           // acquire side
        float z = __ldcg(&g_lam[m0 + tid]) + b2[0];
        out[(size_t)BT_ * V_ + m0 + tid] = 1.0f / (1.0f + __expf(-z));
    }
}

// ---------------- launch ----------------------------------------------------
extern "C" void kernel_launch(void* const* d_in, const int* in_sizes, int n_in,
                              void* d_out, int out_size)
{
    const float* q    = (const float*)d_in[0];
    const float* keys = (const float*)d_in[1];
    const float* dist = (const float*)d_in[2];
    const int*   vals = (const int*)d_in[3];
    const float* Wb   = (const float*)d_in[4];
    const float* bb   = (const float*)d_in[5];
    const float* W1   = (const float*)d_in[6];
    const float* b1   = (const float*)d_in[7];
    const float* W2   = (const float*)d_in[8];
    const float* b2   = (const float*)d_in[9];
    float* out = (float*)d_out;

    cudaFuncSetAttribute(gemm_kernel, cudaFuncAttributeMaxDynamicSharedMemorySize,
                         GEMM_SMEM_BYTES);
    cudaFuncSetAttribute(fuse_kernel, cudaFuncAttributeMaxDynamicSharedMemorySize,
                         FUSE_SMEM_BYTES);

    // 1. convert W1 to fp16 hi/lo; zero lambda accumulators + counters
    convw_kernel<<<2048, 256>>>(W1);

    // 2. fused zero+bandwidth+softmax+scatter+weighted-sum (persistent,
    //    3 CTAs/SM; 36/64 k-slices cached fp16 in smem for pass 2) — R14 config
    fuse_kernel<<<444, 256, FUSE_SMEM_BYTES>>>(q, keys, dist, vals, Wb, bb, out);

    // 3. relu(X @ W1 + b1) via fp16 2-term MMA, 3-stage pipeline (under test);
    //    epilogue accumulates h.W2, last CTA per m-slab writes sigmoid(lambda)
    gemm_kernel<<<dim3(D_ / BN, BT_ / BM), 256, GEMM_SMEM_BYTES>>>(b1, W2, b2, out);
}